// round 3
// baseline (speedup 1.0000x reference)
#include <cuda_runtime.h>

#define BATCH 32
#define CH    256
#define SEQ   1024
#define NH    4
#define DH    64
#define QKSCALE 0.125f   // 1/sqrt(64)

// Scratch (device globals: allocation-free per harness rules)
__device__ float g_Q[BATCH*NH*SEQ*DH];   // [b,h,s,d], pre-scaled by QKSCALE
__device__ float g_K[BATCH*NH*DH*SEQ];   // [b,h,d,s]  (transposed)
__device__ float g_V[BATCH*NH*SEQ*DH];   // [b,h,s,d]
__device__ float g_O[BATCH*SEQ*CH];      // [b,s,h*d]

__device__ __forceinline__ float f4c(const float4& v, int k) {
    return k == 0 ? v.x : k == 1 ? v.y : k == 2 ? v.z : v.w;
}

// ---------------------------------------------------------------------------
// Kernel 1: qkv = xs @ W_qkv + b_qkv ; scatter into g_Q (scaled), g_K^T, g_V
// xs[b,s,c] = x[b,c,s].  M=32768, N=768, K=256. Tiles 64x64x16, 256 threads.
// ---------------------------------------------------------------------------
__global__ __launch_bounds__(256) void qkv_gemm(
    const float* __restrict__ x, const float* __restrict__ Wqkv,
    const float* __restrict__ bqkv)
{
    __shared__ float As[16][64];   // [k][m]
    __shared__ float Bs[16][64];   // [k][n]
    const int m0 = blockIdx.x * 64;       // 512
    const int n0 = blockIdx.y * 64;       // 12
    const int b  = m0 >> 10;
    const int s0 = m0 & 1023;
    const int tid = threadIdx.x;
    const int tx = tid & 15, ty = tid >> 4;

    float acc[4][4] = {};
    const int lkk = tid >> 4;
    const int lmm = (tid & 15) << 2;

    for (int k0 = 0; k0 < 256; k0 += 16) {
        float4 av = *(const float4*)&x[((b << 8) + k0 + lkk) * 1024 + s0 + lmm];
        float4 bv = *(const float4*)&Wqkv[(k0 + lkk) * 768 + n0 + lmm];
        *(float4*)&As[lkk][lmm] = av;
        *(float4*)&Bs[lkk][lmm] = bv;
        __syncthreads();
        #pragma unroll
        for (int kk = 0; kk < 16; kk++) {
            float4 a = *(float4*)&As[kk][ty << 2];
            float4 w = *(float4*)&Bs[kk][tx << 2];
            float aa[4] = {a.x, a.y, a.z, a.w};
            float ww[4] = {w.x, w.y, w.z, w.w};
            #pragma unroll
            for (int i = 0; i < 4; i++)
                #pragma unroll
                for (int j = 0; j < 4; j++)
                    acc[i][j] += aa[i] * ww[j];
        }
        __syncthreads();
    }

    // Epilogue: n-tile -> (type, head).  cols of one 64-tile are one (type,head).
    const int type = (n0 >> 6) % 3;       // 0=q 1=k 2=v
    const int head = n0 / 192;
    const int bh   = (b << 2) + head;
    const int d0   = tx << 2;
    float bias[4];
    #pragma unroll
    for (int j = 0; j < 4; j++) bias[j] = bqkv[n0 + d0 + j];

    if (type == 0) {
        #pragma unroll
        for (int i = 0; i < 4; i++) {
            int srow = s0 + (ty << 2) + i;
            float4 v = make_float4((acc[i][0] + bias[0]) * QKSCALE,
                                   (acc[i][1] + bias[1]) * QKSCALE,
                                   (acc[i][2] + bias[2]) * QKSCALE,
                                   (acc[i][3] + bias[3]) * QKSCALE);
            *(float4*)&g_Q[((bh << 10) + srow) * 64 + d0] = v;
        }
    } else if (type == 2) {
        #pragma unroll
        for (int i = 0; i < 4; i++) {
            int srow = s0 + (ty << 2) + i;
            float4 v = make_float4(acc[i][0] + bias[0], acc[i][1] + bias[1],
                                   acc[i][2] + bias[2], acc[i][3] + bias[3]);
            *(float4*)&g_V[((bh << 10) + srow) * 64 + d0] = v;
        }
    } else {
        // K: transposed store [b,h,d,s]; pack 4 consecutive s per float4
        #pragma unroll
        for (int j = 0; j < 4; j++) {
            float4 v = make_float4(acc[0][j] + bias[j], acc[1][j] + bias[j],
                                   acc[2][j] + bias[j], acc[3][j] + bias[j]);
            *(float4*)&g_K[((bh << 6) + d0 + j) * 1024 + s0 + (ty << 2)] = v;
        }
    }
}

// ---------------------------------------------------------------------------
// Kernel 2: flash attention, fp32.  CTA = (qtile 64, bh).  256 threads.
// Qs[64][64] linear; Kt[64 d][68] (from transposed g_K); Vs[64 c][68];
// Ps[64 r][68].  Online softmax; O accum in regs (2 rows x 8 dims / thread).
// ---------------------------------------------------------------------------
__global__ __launch_bounds__(256, 2) void flash_attn()
{
    extern __shared__ float smem[];
    float* Qs  = smem;                 // 64*64
    float* Kt  = Qs + 64 * 64;         // 64*68
    float* Vs  = Kt + 64 * 68;         // 64*68
    float* Ps  = Vs + 64 * 68;         // 64*68
    float* m_s = Ps + 64 * 68;         // 64
    float* l_s = m_s + 64;             // 64
    float* a_s = l_s + 64;             // 64

    const int qt  = blockIdx.x;        // 16
    const int bh  = blockIdx.y;        // 128
    const int tid = threadIdx.x;

    // score-phase mapping: 4x4 block
    const int r0 = (tid >> 4) << 2;
    const int c0 = (tid & 15) << 2;
    // softmax mapping: 4 lanes per row
    const int sr = tid >> 2, part = tid & 3;
    const int cb = part << 4;
    // O-phase mapping: rows (rA, rA+32), 8 dims
    const int rA = tid >> 3;
    const int dc = tid & 7;

    // load Q tile
    const float* Qg = g_Q + ((bh << 10) + (qt << 6)) * 64;
    #pragma unroll
    for (int i = 0; i < 4; i++) {
        int lin = tid + i * 256;
        int r = lin >> 4, c4 = (lin & 15) << 2;
        *(float4*)&Qs[r * 64 + c4] = *(const float4*)&Qg[r * 64 + c4];
    }
    if (tid < 64) { m_s[tid] = -1e30f; l_s[tid] = 0.0f; }

    float o[16] = {};

    const float* Kg0 = g_K + (bh << 6) * 1024;           // [d][s]
    const float* Vg0 = g_V + (bh << 10) * 64;            // [s][d]

    for (int kt = 0; kt < 16; kt++) {
        __syncthreads();   // prior O-update done with Vs/Ps
        const float* Kg = Kg0 + (kt << 6);
        const float* Vg = Vg0 + (kt << 6) * 64;
        #pragma unroll
        for (int i = 0; i < 4; i++) {
            int lin = tid + i * 256;
            int r = lin >> 4, c4 = (lin & 15) << 2;
            *(float4*)&Kt[r * 68 + c4] = *(const float4*)&Kg[r * 1024 + c4];
            *(float4*)&Vs[r * 68 + c4] = *(const float4*)&Vg[r * 64 + c4];
        }
        __syncthreads();

        // scores (Q pre-scaled)
        float sacc[4][4] = {};
        #pragma unroll 4
        for (int k4 = 0; k4 < 16; k4++) {
            float4 q0 = *(float4*)&Qs[(r0 + 0) * 64 + (k4 << 2)];
            float4 q1 = *(float4*)&Qs[(r0 + 1) * 64 + (k4 << 2)];
            float4 q2 = *(float4*)&Qs[(r0 + 2) * 64 + (k4 << 2)];
            float4 q3 = *(float4*)&Qs[(r0 + 3) * 64 + (k4 << 2)];
            #pragma unroll
            for (int kk = 0; kk < 4; kk++) {
                float4 kv = *(float4*)&Kt[((k4 << 2) + kk) * 68 + c0];
                float kc[4] = {kv.x, kv.y, kv.z, kv.w};
                float qa[4] = {f4c(q0, kk), f4c(q1, kk), f4c(q2, kk), f4c(q3, kk)};
                #pragma unroll
                for (int i = 0; i < 4; i++)
                    #pragma unroll
                    for (int j = 0; j < 4; j++)
                        sacc[i][j] += qa[i] * kc[j];
            }
        }
        #pragma unroll
        for (int i = 0; i < 4; i++)
            *(float4*)&Ps[(r0 + i) * 68 + c0] =
                make_float4(sacc[i][0], sacc[i][1], sacc[i][2], sacc[i][3]);
        __syncthreads();

        // online softmax
        {
            float m_old = m_s[sr];
            float mx = -1e30f;
            #pragma unroll
            for (int i = 0; i < 16; i++) mx = fmaxf(mx, Ps[sr * 68 + cb + i]);
            mx = fmaxf(mx, __shfl_xor_sync(0xffffffffu, mx, 1));
            mx = fmaxf(mx, __shfl_xor_sync(0xffffffffu, mx, 2));
            float m_new = fmaxf(m_old, mx);
            float sum = 0.0f;
            #pragma unroll
            for (int i = 0; i < 16; i++) {
                float p = __expf(Ps[sr * 68 + cb + i] - m_new);
                Ps[sr * 68 + cb + i] = p;
                sum += p;
            }
            sum += __shfl_xor_sync(0xffffffffu, sum, 1);
            sum += __shfl_xor_sync(0xffffffffu, sum, 2);
            if (part == 0) {
                float al = __expf(m_old - m_new);
                a_s[sr] = al;
                m_s[sr] = m_new;
                l_s[sr] = l_s[sr] * al + sum;
            }
        }
        __syncthreads();

        // O += P @ V
        {
            float al0 = a_s[rA], al1 = a_s[rA + 32];
            #pragma unroll
            for (int j = 0; j < 8; j++) { o[j] *= al0; o[8 + j] *= al1; }
            #pragma unroll 4
            for (int c = 0; c < 64; c++) {
                float p0 = Ps[rA * 68 + c];
                float p1 = Ps[(rA + 32) * 68 + c];
                float4 v0 = *(float4*)&Vs[c * 68 + (dc << 3)];
                float4 v1 = *(float4*)&Vs[c * 68 + (dc << 3) + 4];
                o[0] += p0 * v0.x; o[1] += p0 * v0.y; o[2] += p0 * v0.z; o[3] += p0 * v0.w;
                o[4] += p0 * v1.x; o[5] += p0 * v1.y; o[6] += p0 * v1.z; o[7] += p0 * v1.w;
                o[8]  += p1 * v0.x; o[9]  += p1 * v0.y; o[10] += p1 * v0.z; o[11] += p1 * v0.w;
                o[12] += p1 * v1.x; o[13] += p1 * v1.y; o[14] += p1 * v1.z; o[15] += p1 * v1.w;
            }
        }
    }

    // epilogue: normalize, write [b,s,h*64+d]
    const float inv0 = 1.0f / l_s[rA];
    const float inv1 = 1.0f / l_s[rA + 32];
    const int b = bh >> 2, h = bh & 3;
    const int s0 = (qt << 6);
    float* O0 = g_O + ((b << 10) + s0 + rA) * 256 + (h << 6) + (dc << 3);
    float* O1 = g_O + ((b << 10) + s0 + rA + 32) * 256 + (h << 6) + (dc << 3);
    *(float4*)O0       = make_float4(o[0]*inv0, o[1]*inv0, o[2]*inv0, o[3]*inv0);
    *(float4*)(O0 + 4) = make_float4(o[4]*inv0, o[5]*inv0, o[6]*inv0, o[7]*inv0);
    *(float4*)O1       = make_float4(o[8]*inv1, o[9]*inv1, o[10]*inv1, o[11]*inv1);
    *(float4*)(O1 + 4) = make_float4(o[12]*inv1, o[13]*inv1, o[14]*inv1, o[15]*inv1);
}

// ---------------------------------------------------------------------------
// Kernel 3: out = O @ W_out + b_out + xs, written transposed -> [b,c,s]
// ---------------------------------------------------------------------------
__global__ __launch_bounds__(256) void out_gemm(
    const float* __restrict__ x, const float* __restrict__ Wout,
    const float* __restrict__ bout, float* __restrict__ out)
{
    __shared__ float As2[64][17];   // [m][k]
    __shared__ float Bs[16][64];    // [k][n]
    __shared__ float Cs[64][68];    // [m=s][n]
    const int m0 = blockIdx.x * 64;      // 512
    const int n0 = blockIdx.y * 64;      // 4
    const int b  = m0 >> 10;
    const int s0 = m0 & 1023;
    const int tid = threadIdx.x;
    const int tx = tid & 15, ty = tid >> 4;

    float acc[4][4] = {};
    const int arow = tid >> 2;
    const int akk  = (tid & 3) << 2;
    const int bkk  = tid >> 4;
    const int bnn  = (tid & 15) << 2;

    for (int k0 = 0; k0 < 256; k0 += 16) {
        float4 av = *(const float4*)&g_O[(m0 + arow) * 256 + k0 + akk];
        As2[arow][akk] = av.x; As2[arow][akk + 1] = av.y;
        As2[arow][akk + 2] = av.z; As2[arow][akk + 3] = av.w;
        *(float4*)&Bs[bkk][bnn] = *(const float4*)&Wout[(k0 + bkk) * 256 + n0 + bnn];
        __syncthreads();
        #pragma unroll
        for (int kk = 0; kk < 16; kk++) {
            float aa[4];
            #pragma unroll
            for (int i = 0; i < 4; i++) aa[i] = As2[(ty << 2) + i][kk];
            float4 w = *(float4*)&Bs[kk][tx << 2];
            float ww[4] = {w.x, w.y, w.z, w.w};
            #pragma unroll
            for (int i = 0; i < 4; i++)
                #pragma unroll
                for (int j = 0; j < 4; j++)
                    acc[i][j] += aa[i] * ww[j];
        }
        __syncthreads();
    }

    // stage tile, then coalesced transposed write + bias + residual
    #pragma unroll
    for (int i = 0; i < 4; i++)
        *(float4*)&Cs[(ty << 2) + i][tx << 2] =
            make_float4(acc[i][0], acc[i][1], acc[i][2], acc[i][3]);
    __syncthreads();

    #pragma unroll
    for (int i = 0; i < 4; i++) {
        int lin = tid + i * 256;
        int n  = lin >> 4;
        int s4 = (lin & 15) << 2;
        float bb = bout[n0 + n];
        float4 cv = make_float4(Cs[s4][n], Cs[s4 + 1][n], Cs[s4 + 2][n], Cs[s4 + 3][n]);
        int gidx = ((b << 8) + n0 + n) * 1024 + s0 + s4;
        float4 xv = *(const float4*)&x[gidx];
        *(float4*)&out[gidx] = make_float4(cv.x + bb + xv.x, cv.y + bb + xv.y,
                                           cv.z + bb + xv.z, cv.w + bb + xv.w);
    }
}

// ---------------------------------------------------------------------------
extern "C" void kernel_launch(void* const* d_in, const int* in_sizes, int n_in,
                              void* d_out, int out_size)
{
    const float* x    = (const float*)d_in[0];
    const float* Wqkv = (const float*)d_in[1];
    const float* bqkv = (const float*)d_in[2];
    const float* Wout = (const float*)d_in[3];
    const float* bout = (const float*)d_in[4];
    float* out = (float*)d_out;

    qkv_gemm<<<dim3(512, 12), 256>>>(x, Wqkv, bqkv);

    size_t smem = (size_t)(64 * 64 + 3 * 64 * 68 + 3 * 64) * sizeof(float);
    cudaFuncSetAttribute(flash_attn, cudaFuncAttributeMaxDynamicSharedMemorySize,
                         (int)smem);
    flash_attn<<<dim3(16, 128), 256, smem>>>();

    out_gemm<<<dim3(512, 4), 256>>>(x, Wout, bout, out);
}

// round 4
// speedup vs baseline: 1.7594x; 1.7594x over previous
#include <cuda_runtime.h>
#include <cuda_bf16.h>

#define BATCH 32
#define CH    256
#define SEQ   1024
#define NH    4
#define DH    64
#define QKSCALE 0.125f   // 1/sqrt(64)

// Scratch (device globals: allocation-free per harness rules)
__device__ __nv_bfloat16 g_Qh[BATCH*NH*SEQ*DH];   // [b,h,s,d] bf16, pre-scaled
__device__ __nv_bfloat16 g_Kh[BATCH*NH*SEQ*DH];   // [b,h,s,d] bf16
__device__ __nv_bfloat16 g_Vth[BATCH*NH*DH*SEQ];  // [b,h,d,s] bf16 (transposed)
__device__ float g_O[BATCH*SEQ*CH];               // [b,s,h*d] fp32

__device__ __forceinline__ unsigned pack_bf16(float a, float b) {
    __nv_bfloat162 h = __floats2bfloat162_rn(a, b);
    return *reinterpret_cast<unsigned*>(&h);
}

__device__ __forceinline__ void mma16816(float* c, const unsigned* a,
                                         unsigned b0, unsigned b1) {
    asm volatile(
        "mma.sync.aligned.m16n8k16.row.col.f32.bf16.bf16.f32 "
        "{%0,%1,%2,%3}, {%4,%5,%6,%7}, {%8,%9}, {%0,%1,%2,%3};\n"
        : "+f"(c[0]), "+f"(c[1]), "+f"(c[2]), "+f"(c[3])
        : "r"(a[0]), "r"(a[1]), "r"(a[2]), "r"(a[3]), "r"(b0), "r"(b1));
}

// ---------------------------------------------------------------------------
// Kernel 1: qkv = xs @ W_qkv + b_qkv ; scatter into bf16 Q (scaled), K, V^T
// xs[b,s,c] = x[b,c,s].  M=32768, N=768, K=256. Tiles 64x64x16, 256 threads.
// ---------------------------------------------------------------------------
__global__ __launch_bounds__(256) void qkv_gemm(
    const float* __restrict__ x, const float* __restrict__ Wqkv,
    const float* __restrict__ bqkv)
{
    __shared__ float As[16][64];   // [k][m]
    __shared__ float Bs[16][64];   // [k][n]
    const int m0 = blockIdx.x * 64;       // 512
    const int n0 = blockIdx.y * 64;       // 12
    const int b  = m0 >> 10;
    const int s0 = m0 & 1023;
    const int tid = threadIdx.x;
    const int tx = tid & 15, ty = tid >> 4;

    float acc[4][4] = {};
    const int lkk = tid >> 4;
    const int lmm = (tid & 15) << 2;

    for (int k0 = 0; k0 < 256; k0 += 16) {
        float4 av = *(const float4*)&x[((b << 8) + k0 + lkk) * 1024 + s0 + lmm];
        float4 bv = *(const float4*)&Wqkv[(k0 + lkk) * 768 + n0 + lmm];
        *(float4*)&As[lkk][lmm] = av;
        *(float4*)&Bs[lkk][lmm] = bv;
        __syncthreads();
        #pragma unroll
        for (int kk = 0; kk < 16; kk++) {
            float4 a = *(float4*)&As[kk][ty << 2];
            float4 w = *(float4*)&Bs[kk][tx << 2];
            float aa[4] = {a.x, a.y, a.z, a.w};
            float ww[4] = {w.x, w.y, w.z, w.w};
            #pragma unroll
            for (int i = 0; i < 4; i++)
                #pragma unroll
                for (int j = 0; j < 4; j++)
                    acc[i][j] += aa[i] * ww[j];
        }
        __syncthreads();
    }

    const int type = (n0 >> 6) % 3;       // 0=q 1=k 2=v
    const int head = n0 / 192;
    const int bh   = (b << 2) + head;
    const int d0   = tx << 2;
    float bias[4];
    #pragma unroll
    for (int j = 0; j < 4; j++) bias[j] = bqkv[n0 + d0 + j];

    if (type == 0) {
        #pragma unroll
        for (int i = 0; i < 4; i++) {
            int srow = s0 + (ty << 2) + i;
            uint2 pk;
            pk.x = pack_bf16((acc[i][0] + bias[0]) * QKSCALE,
                             (acc[i][1] + bias[1]) * QKSCALE);
            pk.y = pack_bf16((acc[i][2] + bias[2]) * QKSCALE,
                             (acc[i][3] + bias[3]) * QKSCALE);
            *(uint2*)&g_Qh[((bh << 10) + srow) * 64 + d0] = pk;
        }
    } else if (type == 1) {
        #pragma unroll
        for (int i = 0; i < 4; i++) {
            int srow = s0 + (ty << 2) + i;
            uint2 pk;
            pk.x = pack_bf16(acc[i][0] + bias[0], acc[i][1] + bias[1]);
            pk.y = pack_bf16(acc[i][2] + bias[2], acc[i][3] + bias[3]);
            *(uint2*)&g_Kh[((bh << 10) + srow) * 64 + d0] = pk;
        }
    } else {
        // V transposed: [b,h,d,s]; pack 4 consecutive s per uint2
        #pragma unroll
        for (int j = 0; j < 4; j++) {
            uint2 pk;
            pk.x = pack_bf16(acc[0][j] + bias[j], acc[1][j] + bias[j]);
            pk.y = pack_bf16(acc[2][j] + bias[j], acc[3][j] + bias[j]);
            *(uint2*)&g_Vth[((bh << 6) + d0 + j) * 1024 + s0 + (ty << 2)] = pk;
        }
    }
}

// ---------------------------------------------------------------------------
// Kernel 2: flash attention, bf16 HMMA (mma.sync m16n8k16), fp32 softmax.
// CTA = (64-query tile, bh), 256 threads = 8 warps.
// Warp w: rows rw*16 (rw=w>>1), cols cw*32 (cw=w&1) of the 64x64 tiles.
// Smem bf16 tiles use stride 72 (conflict-free 4B fragment loads);
// Ps fp32 stride 72 (conflict-free float2 score stores).
// ---------------------------------------------------------------------------
#define SB 72

__global__ __launch_bounds__(256, 2) void flash_attn()
{
    extern __shared__ char smraw[];
    __nv_bfloat16* Ks = (__nv_bfloat16*)smraw;        // 64*SB
    __nv_bfloat16* Vt = Ks + 64 * SB;                 // 64*SB
    __nv_bfloat16* Ph = Vt + 64 * SB;                 // 64*SB
    float* Ps  = (float*)(Ph + 64 * SB);              // 64*SB f32
    float* m_s = Ps + 64 * SB;
    float* l_s = m_s + 64;
    float* a_s = l_s + 64;

    const int qt  = blockIdx.x;        // 16
    const int bh  = blockIdx.y;        // 128
    const int tid = threadIdx.x;
    const int w   = tid >> 5, lane = tid & 31;
    const int g   = lane >> 2, tg = lane & 3;
    const int rw  = w >> 1, cw = w & 1;
    const int qr0 = rw << 4;

    // Q fragments, held in registers for the whole kernel
    const __nv_bfloat16* Qg = g_Qh + ((bh << 10) + (qt << 6)) * 64;
    unsigned qa[4][4];
    #pragma unroll
    for (int kk = 0; kk < 4; kk++) {
        int c = (kk << 4) + (tg << 1);
        qa[kk][0] = *(const unsigned*)&Qg[(qr0 + g) * 64 + c];
        qa[kk][1] = *(const unsigned*)&Qg[(qr0 + g + 8) * 64 + c];
        qa[kk][2] = *(const unsigned*)&Qg[(qr0 + g) * 64 + c + 8];
        qa[kk][3] = *(const unsigned*)&Qg[(qr0 + g + 8) * 64 + c + 8];
    }

    if (tid < 64) { m_s[tid] = -1e30f; l_s[tid] = 0.0f; }

    float o[4][4] = {};

    const __nv_bfloat16* Kg0 = g_Kh  + (bh << 10) * 64;    // [s][d]
    const __nv_bfloat16* Vg0 = g_Vth + (bh << 6) * 1024;   // [d][s]

    for (int kt = 0; kt < 16; kt++) {
        __syncthreads();   // previous PV finished reading Ph/Vt
        {
            const __nv_bfloat16* Kg = Kg0 + (kt << 6) * 64;
            const __nv_bfloat16* Vg = Vg0 + (kt << 6);
            #pragma unroll
            for (int i = 0; i < 4; i++) {
                int idx = tid + i * 256;          // 1024 uint2 groups
                int r  = idx >> 4;
                int c4 = (idx & 15) << 2;
                *(uint2*)&Ks[r * SB + c4] = *(const uint2*)&Kg[r * 64 + c4];
                *(uint2*)&Vt[r * SB + c4] = *(const uint2*)&Vg[r * 1024 + c4];
            }
        }
        __syncthreads();

        // scores: S = Q K^T  (Q pre-scaled)
        float sc[4][4];
        #pragma unroll
        for (int t = 0; t < 4; t++)
            #pragma unroll
            for (int i = 0; i < 4; i++) sc[t][i] = 0.0f;
        #pragma unroll
        for (int t = 0; t < 4; t++) {
            int j = (cw << 5) + (t << 3) + g;
            #pragma unroll
            for (int kk = 0; kk < 4; kk++) {
                int d = (kk << 4) + (tg << 1);
                unsigned b0 = *(const unsigned*)&Ks[j * SB + d];
                unsigned b1 = *(const unsigned*)&Ks[j * SB + d + 8];
                mma16816(sc[t], qa[kk], b0, b1);
            }
        }
        #pragma unroll
        for (int t = 0; t < 4; t++) {
            int col = (cw << 5) + (t << 3) + (tg << 1);
            *(float2*)&Ps[(qr0 + g) * SB + col]     = make_float2(sc[t][0], sc[t][1]);
            *(float2*)&Ps[(qr0 + g + 8) * SB + col] = make_float2(sc[t][2], sc[t][3]);
        }
        __syncthreads();

        // online softmax (fp32), write P as bf16
        {
            int sr = tid >> 2, part = tid & 3, cb = part << 4;
            float m_old = m_s[sr];
            float mx = -1e30f;
            #pragma unroll
            for (int i = 0; i < 16; i++) mx = fmaxf(mx, Ps[sr * SB + cb + i]);
            mx = fmaxf(mx, __shfl_xor_sync(0xffffffffu, mx, 1));
            mx = fmaxf(mx, __shfl_xor_sync(0xffffffffu, mx, 2));
            float m_new = fmaxf(m_old, mx);
            float sum = 0.0f;
            #pragma unroll
            for (int i = 0; i < 8; i++) {
                float p0 = __expf(Ps[sr * SB + cb + 2 * i]     - m_new);
                float p1 = __expf(Ps[sr * SB + cb + 2 * i + 1] - m_new);
                sum += p0 + p1;
                *(unsigned*)&Ph[sr * SB + cb + 2 * i] = pack_bf16(p0, p1);
            }
            sum += __shfl_xor_sync(0xffffffffu, sum, 1);
            sum += __shfl_xor_sync(0xffffffffu, sum, 2);
            if (part == 0) {
                float al = __expf(m_old - m_new);
                a_s[sr] = al;
                m_s[sr] = m_new;
                l_s[sr] = l_s[sr] * al + sum;
            }
        }
        __syncthreads();

        // O = O*alpha + P V
        {
            float al0 = a_s[qr0 + g], al8 = a_s[qr0 + g + 8];
            #pragma unroll
            for (int t = 0; t < 4; t++) {
                o[t][0] *= al0; o[t][1] *= al0;
                o[t][2] *= al8; o[t][3] *= al8;
            }
            unsigned pa[4][4];
            #pragma unroll
            for (int kk = 0; kk < 4; kk++) {
                int j = (kk << 4) + (tg << 1);
                pa[kk][0] = *(const unsigned*)&Ph[(qr0 + g) * SB + j];
                pa[kk][1] = *(const unsigned*)&Ph[(qr0 + g + 8) * SB + j];
                pa[kk][2] = *(const unsigned*)&Ph[(qr0 + g) * SB + j + 8];
                pa[kk][3] = *(const unsigned*)&Ph[(qr0 + g + 8) * SB + j + 8];
            }
            #pragma unroll
            for (int t = 0; t < 4; t++) {
                int dc = (cw << 5) + (t << 3) + g;
                #pragma unroll
                for (int kk = 0; kk < 4; kk++) {
                    int j = (kk << 4) + (tg << 1);
                    unsigned b0 = *(const unsigned*)&Vt[dc * SB + j];
                    unsigned b1 = *(const unsigned*)&Vt[dc * SB + j + 8];
                    mma16816(o[t], pa[kk], b0, b1);
                }
            }
        }
    }

    // epilogue: normalize, write [b, s, h*64+d] fp32
    const float inv0 = 1.0f / l_s[qr0 + g];
    const float inv8 = 1.0f / l_s[qr0 + g + 8];
    const int b = bh >> 2, h = bh & 3;
    const int s0 = qt << 6;
    #pragma unroll
    for (int t = 0; t < 4; t++) {
        int col = (h << 6) + (cw << 5) + (t << 3) + (tg << 1);
        float* O0 = g_O + ((b << 10) + s0 + qr0 + g) * 256 + col;
        float* O8 = g_O + ((b << 10) + s0 + qr0 + g + 8) * 256 + col;
        *(float2*)O0 = make_float2(o[t][0] * inv0, o[t][1] * inv0);
        *(float2*)O8 = make_float2(o[t][2] * inv8, o[t][3] * inv8);
    }
}

// ---------------------------------------------------------------------------
// Kernel 3: out = O @ W_out + b_out + xs, written transposed -> [b,c,s]
// ---------------------------------------------------------------------------
__global__ __launch_bounds__(256) void out_gemm(
    const float* __restrict__ x, const float* __restrict__ Wout,
    const float* __restrict__ bout, float* __restrict__ out)
{
    __shared__ float As2[64][17];   // [m][k]
    __shared__ float Bs[16][64];    // [k][n]
    __shared__ float Cs[64][68];    // [m=s][n]
    const int m0 = blockIdx.x * 64;      // 512
    const int n0 = blockIdx.y * 64;      // 4
    const int b  = m0 >> 10;
    const int s0 = m0 & 1023;
    const int tid = threadIdx.x;
    const int tx = tid & 15, ty = tid >> 4;

    float acc[4][4] = {};
    const int arow = tid >> 2;
    const int akk  = (tid & 3) << 2;
    const int bkk  = tid >> 4;
    const int bnn  = (tid & 15) << 2;

    for (int k0 = 0; k0 < 256; k0 += 16) {
        float4 av = *(const float4*)&g_O[(m0 + arow) * 256 + k0 + akk];
        As2[arow][akk] = av.x; As2[arow][akk + 1] = av.y;
        As2[arow][akk + 2] = av.z; As2[arow][akk + 3] = av.w;
        *(float4*)&Bs[bkk][bnn] = *(const float4*)&Wout[(k0 + bkk) * 256 + n0 + bnn];
        __syncthreads();
        #pragma unroll
        for (int kk = 0; kk < 16; kk++) {
            float aa[4];
            #pragma unroll
            for (int i = 0; i < 4; i++) aa[i] = As2[(ty << 2) + i][kk];
            float4 wv = *(float4*)&Bs[kk][tx << 2];
            float ww[4] = {wv.x, wv.y, wv.z, wv.w};
            #pragma unroll
            for (int i = 0; i < 4; i++)
                #pragma unroll
                for (int j = 0; j < 4; j++)
                    acc[i][j] += aa[i] * ww[j];
        }
        __syncthreads();
    }

    #pragma unroll
    for (int i = 0; i < 4; i++)
        *(float4*)&Cs[(ty << 2) + i][tx << 2] =
            make_float4(acc[i][0], acc[i][1], acc[i][2], acc[i][3]);
    __syncthreads();

    #pragma unroll
    for (int i = 0; i < 4; i++) {
        int lin = tid + i * 256;
        int n  = lin >> 4;
        int s4 = (lin & 15) << 2;
        float bb = bout[n0 + n];
        float4 cv = make_float4(Cs[s4][n], Cs[s4 + 1][n], Cs[s4 + 2][n], Cs[s4 + 3][n]);
        int gidx = ((b << 8) + n0 + n) * 1024 + s0 + s4;
        float4 xv = *(const float4*)&x[gidx];
        *(float4*)&out[gidx] = make_float4(cv.x + bb + xv.x, cv.y + bb + xv.y,
                                           cv.z + bb + xv.z, cv.w + bb + xv.w);
    }
}

// ---------------------------------------------------------------------------
extern "C" void kernel_launch(void* const* d_in, const int* in_sizes, int n_in,
                              void* d_out, int out_size)
{
    const float* x    = (const float*)d_in[0];
    const float* Wqkv = (const float*)d_in[1];
    const float* bqkv = (const float*)d_in[2];
    const float* Wout = (const float*)d_in[3];
    const float* bout = (const float*)d_in[4];
    float* out = (float*)d_out;

    qkv_gemm<<<dim3(512, 12), 256>>>(x, Wqkv, bqkv);

    size_t smem = (size_t)(3 * 64 * SB) * sizeof(__nv_bfloat16)
                + (size_t)(64 * SB + 3 * 64) * sizeof(float);
    cudaFuncSetAttribute(flash_attn, cudaFuncAttributeMaxDynamicSharedMemorySize,
                         (int)smem);
    flash_attn<<<dim3(16, 128), 256, smem>>>();

    out_gemm<<<dim3(512, 4), 256>>>(x, Wout, bout, out);
}

// round 6
// speedup vs baseline: 5.1953x; 2.9529x over previous
#include <cuda_runtime.h>
#include <cuda_bf16.h>

#define BATCH 32
#define CH    256
#define SEQ   1024
#define NH    4
#define DH    64
#define QKSCALE 0.125f   // 1/sqrt(64)

// Scratch (device globals: allocation-free per harness rules)
__device__ __nv_bfloat16 g_Xh[BATCH*SEQ*CH];      // [b,s,c] bf16 (x transposed)
__device__ __nv_bfloat16 g_Wqh[768*CH];           // [n][c] bf16 (Wqkv^T)
__device__ __nv_bfloat16 g_Woh[CH*CH];            // [n][c] bf16 (Wout^T)
__device__ __nv_bfloat16 g_Qh[BATCH*NH*SEQ*DH];   // [b,h,s,d] bf16, pre-scaled
__device__ __nv_bfloat16 g_Kh[BATCH*NH*SEQ*DH];   // [b,h,s,d] bf16
__device__ __nv_bfloat16 g_Vth[BATCH*NH*DH*SEQ];  // [b,h,d,s] bf16 (transposed)
__device__ __nv_bfloat16 g_Oh[BATCH*SEQ*CH];      // [b,s,h*d] bf16

__device__ __forceinline__ unsigned pack_bf16(float a, float b) {
    __nv_bfloat162 h = __floats2bfloat162_rn(a, b);
    return *reinterpret_cast<unsigned*>(&h);
}

__device__ __forceinline__ void mma16816(float* c, const unsigned* a,
                                         unsigned b0, unsigned b1) {
    asm volatile(
        "mma.sync.aligned.m16n8k16.row.col.f32.bf16.bf16.f32 "
        "{%0,%1,%2,%3}, {%4,%5,%6,%7}, {%8,%9}, {%0,%1,%2,%3};\n"
        : "+f"(c[0]), "+f"(c[1]), "+f"(c[2]), "+f"(c[3])
        : "r"(a[0]), "r"(a[1]), "r"(a[2]), "r"(a[3]), "r"(b0), "r"(b1));
}

// ---------------------------------------------------------------------------
// transpose + fp32->bf16 convert:  src[R][C] f32 (slab z)  ->  dst[C][R] bf16
// ---------------------------------------------------------------------------
__global__ __launch_bounds__(256) void transpose_bf16(
    const float* __restrict__ src, __nv_bfloat16* __restrict__ dst,
    int R, int C)
{
    __shared__ float t[32][33];
    const int c0 = blockIdx.x * 32, r0 = blockIdx.y * 32;
    const size_t slab = (size_t)blockIdx.z * R * C;
    const float* s = src + slab;
    __nv_bfloat16* d = dst + slab;
    const int col = threadIdx.x & 31, row8 = threadIdx.x >> 5;
    #pragma unroll
    for (int i = 0; i < 4; i++) {
        int r = row8 + i * 8;
        t[r][col] = s[(size_t)(r0 + r) * C + c0 + col];
    }
    __syncthreads();
    #pragma unroll
    for (int i = 0; i < 4; i++) {
        int cr = row8 + i * 8;
        d[(size_t)(c0 + cr) * R + r0 + col] = __float2bfloat16(t[col][cr]);
    }
}

// ---------------------------------------------------------------------------
// Kernel 1: qkv = Xh @ Wqkv^T + b ; HMMA.  CTA 64x64, K=256 in 4 chunks.
// 8 warps, warp = 16 rows x 32 cols.  Epilogue -> bf16 Q (scaled) / K / V^T.
// ---------------------------------------------------------------------------
#define SA 72   // bf16 smem stride (144B rows: 16B aligned, conflict-free frags)

__global__ __launch_bounds__(256) void qkv_mma(const float* __restrict__ bqkv)
{
    __shared__ __align__(16) char smraw[2 * 64 * SA * 2];  // As+Bs bf16 (18432B)
    __nv_bfloat16* As = (__nv_bfloat16*)smraw;
    __nv_bfloat16* Bs = As + 64 * SA;
    float* Cs = (float*)smraw;                              // reused (17408B)

    const int m0 = blockIdx.x * 64;    // 512
    const int n0 = blockIdx.y * 64;    // 12
    const int b  = m0 >> 10;
    const int s0 = m0 & 1023;
    const int tid = threadIdx.x;
    const int w = tid >> 5, lane = tid & 31;
    const int g = lane >> 2, tg = lane & 3;
    const int rw = w >> 1, cw = w & 1;
    const int qr0 = rw << 4;

    float acc[4][4] = {};

    const __nv_bfloat16* Ag = g_Xh + (size_t)m0 * 256;
    const __nv_bfloat16* Bg = g_Wqh + (size_t)n0 * 256;

    for (int k0 = 0; k0 < 256; k0 += 64) {
        if (k0) __syncthreads();
        #pragma unroll
        for (int i = 0; i < 2; i++) {
            int idx = tid + i * 256;      // 512 uint4 groups of 8 bf16
            int r = idx >> 3, cg = (idx & 7) << 3;
            *(uint4*)&As[r * SA + cg] = *(const uint4*)&Ag[r * 256 + k0 + cg];
            *(uint4*)&Bs[r * SA + cg] = *(const uint4*)&Bg[r * 256 + k0 + cg];
        }
        __syncthreads();
        #pragma unroll
        for (int kk = 0; kk < 4; kk++) {
            const int d = (kk << 4) + (tg << 1);
            unsigned a[4];
            a[0] = *(const unsigned*)&As[(qr0 + g) * SA + d];
            a[1] = *(const unsigned*)&As[(qr0 + g + 8) * SA + d];
            a[2] = *(const unsigned*)&As[(qr0 + g) * SA + d + 8];
            a[3] = *(const unsigned*)&As[(qr0 + g + 8) * SA + d + 8];
            #pragma unroll
            for (int t = 0; t < 4; t++) {
                int j = (cw << 5) + (t << 3) + g;
                unsigned b0 = *(const unsigned*)&Bs[j * SA + d];
                unsigned b1 = *(const unsigned*)&Bs[j * SA + d + 8];
                mma16816(acc[t], a, b0, b1);
            }
        }
    }
    __syncthreads();

    // stage C tile fp32
    #pragma unroll
    for (int t = 0; t < 4; t++) {
        int col = (cw << 5) + (t << 3) + (tg << 1);
        *(float2*)&Cs[(qr0 + g) * 68 + col]     = make_float2(acc[t][0], acc[t][1]);
        *(float2*)&Cs[(qr0 + g + 8) * 68 + col] = make_float2(acc[t][2], acc[t][3]);
    }
    __syncthreads();

    const int type = (n0 >> 6) % 3;    // 0=q 1=k 2=v
    const int head = n0 / 192;
    const int bh   = (b << 2) + head;

    if (type != 2) {
        const int d2 = tid & 31;                   // bf16x2 column index
        const float bb0 = bqkv[n0 + 2 * d2];
        const float bb1 = bqkv[n0 + 2 * d2 + 1];
        const float sc = (type == 0) ? QKSCALE : 1.0f;
        __nv_bfloat16* dst = (type == 0) ? g_Qh : g_Kh;
        #pragma unroll
        for (int i = 0; i < 8; i++) {
            int r = (tid >> 5) + i * 8;
            float f0 = (Cs[r * 68 + 2 * d2]     + bb0) * sc;
            float f1 = (Cs[r * 68 + 2 * d2 + 1] + bb1) * sc;
            *(unsigned*)&dst[((size_t)(bh << 10) + s0 + r) * 64 + 2 * d2] =
                pack_bf16(f0, f1);
        }
    } else {
        const int sp = tid & 31;                   // s-pair index
        #pragma unroll
        for (int i = 0; i < 8; i++) {
            int d = (tid >> 5) + i * 8;
            float bb = bqkv[n0 + d];
            float f0 = Cs[(2 * sp) * 68 + d]     + bb;
            float f1 = Cs[(2 * sp + 1) * 68 + d] + bb;
            *(unsigned*)&g_Vth[((size_t)(bh << 6) + d) * 1024 + s0 + 2 * sp] =
                pack_bf16(f0, f1);
        }
    }
}

// ---------------------------------------------------------------------------
// Kernel 2: flash attention, bf16 HMMA, fp32 softmax. (unchanged from R4
// except O is written bf16)
// ---------------------------------------------------------------------------
#define SB 72

__global__ __launch_bounds__(256, 2) void flash_attn()
{
    extern __shared__ char smraw[];
    __nv_bfloat16* Ks = (__nv_bfloat16*)smraw;        // 64*SB
    __nv_bfloat16* Vt = Ks + 64 * SB;                 // 64*SB
    __nv_bfloat16* Ph = Vt + 64 * SB;                 // 64*SB
    float* Ps  = (float*)(Ph + 64 * SB);              // 64*SB f32
    float* m_s = Ps + 64 * SB;
    float* l_s = m_s + 64;
    float* a_s = l_s + 64;

    const int qt  = blockIdx.x;        // 16
    const int bh  = blockIdx.y;        // 128
    const int tid = threadIdx.x;
    const int w   = tid >> 5, lane = tid & 31;
    const int g   = lane >> 2, tg = lane & 3;
    const int rw  = w >> 1, cw = w & 1;
    const int qr0 = rw << 4;

    const __nv_bfloat16* Qg = g_Qh + ((bh << 10) + (qt << 6)) * 64;
    unsigned qa[4][4];
    #pragma unroll
    for (int kk = 0; kk < 4; kk++) {
        int c = (kk << 4) + (tg << 1);
        qa[kk][0] = *(const unsigned*)&Qg[(qr0 + g) * 64 + c];
        qa[kk][1] = *(const unsigned*)&Qg[(qr0 + g + 8) * 64 + c];
        qa[kk][2] = *(const unsigned*)&Qg[(qr0 + g) * 64 + c + 8];
        qa[kk][3] = *(const unsigned*)&Qg[(qr0 + g + 8) * 64 + c + 8];
    }

    if (tid < 64) { m_s[tid] = -1e30f; l_s[tid] = 0.0f; }

    float o[4][4] = {};

    const __nv_bfloat16* Kg0 = g_Kh  + (bh << 10) * 64;    // [s][d]
    const __nv_bfloat16* Vg0 = g_Vth + (bh << 6) * 1024;   // [d][s]

    for (int kt = 0; kt < 16; kt++) {
        __syncthreads();
        {
            const __nv_bfloat16* Kg = Kg0 + (kt << 6) * 64;
            const __nv_bfloat16* Vg = Vg0 + (kt << 6);
            #pragma unroll
            for (int i = 0; i < 4; i++) {
                int idx = tid + i * 256;
                int r  = idx >> 4;
                int c4 = (idx & 15) << 2;
                *(uint2*)&Ks[r * SB + c4] = *(const uint2*)&Kg[r * 64 + c4];
                *(uint2*)&Vt[r * SB + c4] = *(const uint2*)&Vg[r * 1024 + c4];
            }
        }
        __syncthreads();

        float sc[4][4];
        #pragma unroll
        for (int t = 0; t < 4; t++)
            #pragma unroll
            for (int i = 0; i < 4; i++) sc[t][i] = 0.0f;
        #pragma unroll
        for (int t = 0; t < 4; t++) {
            int j = (cw << 5) + (t << 3) + g;
            #pragma unroll
            for (int kk = 0; kk < 4; kk++) {
                int d = (kk << 4) + (tg << 1);
                unsigned b0 = *(const unsigned*)&Ks[j * SB + d];
                unsigned b1 = *(const unsigned*)&Ks[j * SB + d + 8];
                mma16816(sc[t], qa[kk], b0, b1);
            }
        }
        #pragma unroll
        for (int t = 0; t < 4; t++) {
            int col = (cw << 5) + (t << 3) + (tg << 1);
            *(float2*)&Ps[(qr0 + g) * SB + col]     = make_float2(sc[t][0], sc[t][1]);
            *(float2*)&Ps[(qr0 + g + 8) * SB + col] = make_float2(sc[t][2], sc[t][3]);
        }
        __syncthreads();

        {
            int sr = tid >> 2, part = tid & 3, cb = part << 4;
            float m_old = m_s[sr];
            float mx = -1e30f;
            #pragma unroll
            for (int i = 0; i < 16; i++) mx = fmaxf(mx, Ps[sr * SB + cb + i]);
            mx = fmaxf(mx, __shfl_xor_sync(0xffffffffu, mx, 1));
            mx = fmaxf(mx, __shfl_xor_sync(0xffffffffu, mx, 2));
            float m_new = fmaxf(m_old, mx);
            float sum = 0.0f;
            #pragma unroll
            for (int i = 0; i < 8; i++) {
                float p0 = __expf(Ps[sr * SB + cb + 2 * i]     - m_new);
                float p1 = __expf(Ps[sr * SB + cb + 2 * i + 1] - m_new);
                sum += p0 + p1;
                *(unsigned*)&Ph[sr * SB + cb + 2 * i] = pack_bf16(p0, p1);
            }
            sum += __shfl_xor_sync(0xffffffffu, sum, 1);
            sum += __shfl_xor_sync(0xffffffffu, sum, 2);
            if (part == 0) {
                float al = __expf(m_old - m_new);
                a_s[sr] = al;
                m_s[sr] = m_new;
                l_s[sr] = l_s[sr] * al + sum;
            }
        }
        __syncthreads();

        {
            float al0 = a_s[qr0 + g], al8 = a_s[qr0 + g + 8];
            #pragma unroll
            for (int t = 0; t < 4; t++) {
                o[t][0] *= al0; o[t][1] *= al0;
                o[t][2] *= al8; o[t][3] *= al8;
            }
            unsigned pa[4][4];
            #pragma unroll
            for (int kk = 0; kk < 4; kk++) {
                int j = (kk << 4) + (tg << 1);
                pa[kk][0] = *(const unsigned*)&Ph[(qr0 + g) * SB + j];
                pa[kk][1] = *(const unsigned*)&Ph[(qr0 + g + 8) * SB + j];
                pa[kk][2] = *(const unsigned*)&Ph[(qr0 + g) * SB + j + 8];
                pa[kk][3] = *(const unsigned*)&Ph[(qr0 + g + 8) * SB + j + 8];
            }
            #pragma unroll
            for (int t = 0; t < 4; t++) {
                int dc = (cw << 5) + (t << 3) + g;
                #pragma unroll
                for (int kk = 0; kk < 4; kk++) {
                    int j = (kk << 4) + (tg << 1);
                    unsigned b0 = *(const unsigned*)&Vt[dc * SB + j];
                    unsigned b1 = *(const unsigned*)&Vt[dc * SB + j + 8];
                    mma16816(o[t], pa[kk], b0, b1);
                }
            }
        }
    }

    const float inv0 = 1.0f / l_s[qr0 + g];
    const float inv8 = 1.0f / l_s[qr0 + g + 8];
    const int b = bh >> 2, h = bh & 3;
    const int s0 = qt << 6;
    #pragma unroll
    for (int t = 0; t < 4; t++) {
        int col = (h << 6) + (cw << 5) + (t << 3) + (tg << 1);
        *(unsigned*)&g_Oh[((size_t)(b << 10) + s0 + qr0 + g) * 256 + col] =
            pack_bf16(o[t][0] * inv0, o[t][1] * inv0);
        *(unsigned*)&g_Oh[((size_t)(b << 10) + s0 + qr0 + g + 8) * 256 + col] =
            pack_bf16(o[t][2] * inv8, o[t][3] * inv8);
    }
}

// ---------------------------------------------------------------------------
// Kernel 3: out = Oh @ Wout^T + b_out + xs -> [b,c,s].  HMMA, same structure.
// ---------------------------------------------------------------------------
__global__ __launch_bounds__(256) void out_mma(
    const float* __restrict__ x, const float* __restrict__ bout,
    float* __restrict__ out)
{
    __shared__ __align__(16) char smraw[2 * 64 * SA * 2];
    __nv_bfloat16* As = (__nv_bfloat16*)smraw;
    __nv_bfloat16* Bs = As + 64 * SA;
    float* Cs = (float*)smraw;

    const int m0 = blockIdx.x * 64;    // 512
    const int n0 = blockIdx.y * 64;    // 4
    const int b  = m0 >> 10;
    const int s0 = m0 & 1023;
    const int tid = threadIdx.x;
    const int w = tid >> 5, lane = tid & 31;
    const int g = lane >> 2, tg = lane & 3;
    const int rw = w >> 1, cw = w & 1;
    const int qr0 = rw << 4;

    float acc[4][4] = {};

    const __nv_bfloat16* Ag = g_Oh + (size_t)m0 * 256;
    const __nv_bfloat16* Bg = g_Woh + (size_t)n0 * 256;

    for (int k0 = 0; k0 < 256; k0 += 64) {
        if (k0) __syncthreads();
        #pragma unroll
        for (int i = 0; i < 2; i++) {
            int idx = tid + i * 256;
            int r = idx >> 3, cg = (idx & 7) << 3;
            *(uint4*)&As[r * SA + cg] = *(const uint4*)&Ag[r * 256 + k0 + cg];
            *(uint4*)&Bs[r * SA + cg] = *(const uint4*)&Bg[r * 256 + k0 + cg];
        }
        __syncthreads();
        #pragma unroll
        for (int kk = 0; kk < 4; kk++) {
            const int d = (kk << 4) + (tg << 1);
            unsigned a[4];
            a[0] = *(const unsigned*)&As[(qr0 + g) * SA + d];
            a[1] = *(const unsigned*)&As[(qr0 + g + 8) * SA + d];
            a[2] = *(const unsigned*)&As[(qr0 + g) * SA + d + 8];
            a[3] = *(const unsigned*)&As[(qr0 + g + 8) * SA + d + 8];
            #pragma unroll
            for (int t = 0; t < 4; t++) {
                int j = (cw << 5) + (t << 3) + g;
                unsigned b0 = *(const unsigned*)&Bs[j * SA + d];
                unsigned b1 = *(const unsigned*)&Bs[j * SA + d + 8];
                mma16816(acc[t], a, b0, b1);
            }
        }
    }
    __syncthreads();

    #pragma unroll
    for (int t = 0; t < 4; t++) {
        int col = (cw << 5) + (t << 3) + (tg << 1);
        *(float2*)&Cs[(qr0 + g) * 68 + col]     = make_float2(acc[t][0], acc[t][1]);
        *(float2*)&Cs[(qr0 + g + 8) * 68 + col] = make_float2(acc[t][2], acc[t][3]);
    }
    __syncthreads();

    #pragma unroll
    for (int i = 0; i < 4; i++) {
        int lin = tid + i * 256;
        int n  = lin >> 4;
        int s4 = (lin & 15) << 2;
        float bb = bout[n0 + n];
        float4 cv = make_float4(Cs[s4 * 68 + n], Cs[(s4 + 1) * 68 + n],
                                Cs[(s4 + 2) * 68 + n], Cs[(s4 + 3) * 68 + n]);
        int gidx = ((b << 8) + n0 + n) * 1024 + s0 + s4;
        float4 xv = *(const float4*)&x[gidx];
        *(float4*)&out[gidx] = make_float4(cv.x + bb + xv.x, cv.y + bb + xv.y,
                                           cv.z + bb + xv.z, cv.w + bb + xv.w);
    }
}

// ---------------------------------------------------------------------------
extern "C" void kernel_launch(void* const* d_in, const int* in_sizes, int n_in,
                              void* d_out, int out_size)
{
    const float* x    = (const float*)d_in[0];
    const float* Wqkv = (const float*)d_in[1];
    const float* bqkv = (const float*)d_in[2];
    const float* Wout = (const float*)d_in[3];
    const float* bout = (const float*)d_in[4];
    float* out = (float*)d_out;

    __nv_bfloat16 *pXh, *pWqh, *pWoh;
    cudaGetSymbolAddress((void**)&pXh,  g_Xh);
    cudaGetSymbolAddress((void**)&pWqh, g_Wqh);
    cudaGetSymbolAddress((void**)&pWoh, g_Woh);

    transpose_bf16<<<dim3(32, 8, 32), 256>>>(x,    pXh,  256, 1024);
    transpose_bf16<<<dim3(24, 8, 1),  256>>>(Wqkv, pWqh, 256, 768);
    transpose_bf16<<<dim3(8, 8, 1),   256>>>(Wout, pWoh, 256, 256);

    qkv_mma<<<dim3(512, 12), 256>>>(bqkv);

    size_t smem = (size_t)(3 * 64 * SB) * sizeof(__nv_bfloat16)
                + (size_t)(64 * SB + 3 * 64) * sizeof(float);
    cudaFuncSetAttribute(flash_attn, cudaFuncAttributeMaxDynamicSharedMemorySize,
                         (int)smem);
    flash_attn<<<dim3(16, 128), 256, smem>>>();

    out_mma<<<dim3(512, 4), 256>>>(x, bout, out);
}

// round 8
// speedup vs baseline: 7.6732x; 1.4770x over previous
#include <cuda_runtime.h>
#include <cuda_bf16.h>

#define BATCH 32
#define CH    256
#define SEQ   1024
#define NH    4
#define DH    64
#define QKSCALE 0.125f   // 1/sqrt(64)

// Scratch (device globals: allocation-free per harness rules)
__device__ __nv_bfloat16 g_Xh[BATCH*SEQ*CH];      // [b,s,c] bf16 (x transposed)
__device__ __nv_bfloat16 g_Wqh[768*CH];           // [n][c] bf16 (Wqkv^T)
__device__ __nv_bfloat16 g_Woh[CH*CH];            // [n][c] bf16 (Wout^T)
__device__ __nv_bfloat16 g_Qh[BATCH*NH*SEQ*DH];   // [b,h,s,d] bf16, pre-scaled
__device__ __nv_bfloat16 g_Kh[BATCH*NH*SEQ*DH];   // [b,h,s,d] bf16
__device__ __nv_bfloat16 g_Vth[BATCH*NH*DH*SEQ];  // [b,h,d,s] bf16 (transposed)
__device__ __nv_bfloat16 g_Oh[BATCH*SEQ*CH];      // [b,s,h*d] bf16

__device__ __forceinline__ unsigned pack_bf16(float a, float b) {
    __nv_bfloat162 h = __floats2bfloat162_rn(a, b);
    return *reinterpret_cast<unsigned*>(&h);
}

__device__ __forceinline__ void mma16816(float* c, const unsigned* a,
                                         unsigned b0, unsigned b1) {
    asm volatile(
        "mma.sync.aligned.m16n8k16.row.col.f32.bf16.bf16.f32 "
        "{%0,%1,%2,%3}, {%4,%5,%6,%7}, {%8,%9}, {%0,%1,%2,%3};\n"
        : "+f"(c[0]), "+f"(c[1]), "+f"(c[2]), "+f"(c[3])
        : "r"(a[0]), "r"(a[1]), "r"(a[2]), "r"(a[3]), "r"(b0), "r"(b1));
}

__device__ __forceinline__ void cp16(unsigned dst, const void* src) {
    asm volatile("cp.async.ca.shared.global [%0], [%1], 16;\n"
                 :: "r"(dst), "l"(src));
}
#define CP_COMMIT() asm volatile("cp.async.commit_group;\n")
#define CP_WAIT(n)  asm volatile("cp.async.wait_group %0;\n" :: "n"(n))

// ---------------------------------------------------------------------------
// transpose + fp32->bf16 convert:  src[R][C] f32 (slab z)  ->  dst[C][R] bf16
// ---------------------------------------------------------------------------
__global__ __launch_bounds__(256) void transpose_bf16(
    const float* __restrict__ src, __nv_bfloat16* __restrict__ dst,
    int R, int C)
{
    __shared__ float t[32][33];
    const int c0 = blockIdx.x * 32, r0 = blockIdx.y * 32;
    const size_t slab = (size_t)blockIdx.z * R * C;
    const float* s = src + slab;
    __nv_bfloat16* d = dst + slab;
    const int col = threadIdx.x & 31, row8 = threadIdx.x >> 5;
    #pragma unroll
    for (int i = 0; i < 4; i++) {
        int r = row8 + i * 8;
        t[r][col] = s[(size_t)(r0 + r) * C + c0 + col];
    }
    __syncthreads();
    #pragma unroll
    for (int i = 0; i < 4; i++) {
        int cr = row8 + i * 8;
        d[(size_t)(c0 + cr) * R + r0 + col] = __float2bfloat16(t[col][cr]);
    }
}

#define SA 72   // bf16 smem stride: 144B rows, 16B-aligned, conflict-free frags

// ---------------------------------------------------------------------------
// Kernel 1: qkv = Xh @ Wqkv^T + b ; HMMA.  CTA 128x64, K=256, 4 chunks,
// cp.async double-buffered.  Warp = 16 rows x 64 cols (8 n-tiles).
// ---------------------------------------------------------------------------
__global__ __launch_bounds__(256, 2) void qkv_mma(const float* __restrict__ bqkv)
{
    extern __shared__ __align__(16) char smraw[];
    __nv_bfloat16* As = (__nv_bfloat16*)smraw;        // 2 bufs x 128*SA
    __nv_bfloat16* Bs = As + 2 * 128 * SA;            // 2 bufs x 64*SA
    float* Cs = (float*)smraw;                         // epilogue reuse 128*68

    const int m0 = blockIdx.x * 128;   // grid.x = 256
    const int n0 = blockIdx.y * 64;    // 12
    const int b  = m0 >> 10;
    const int s0 = m0 & 1023;
    const int tid = threadIdx.x;
    const int w = tid >> 5, lane = tid & 31;
    const int g = lane >> 2, tg = lane & 3;
    const int qr0 = w << 4;

    const __nv_bfloat16* Ag = g_Xh + (size_t)m0 * 256;
    const __nv_bfloat16* Bg = g_Wqh + (size_t)n0 * 256;

    const unsigned sA = (unsigned)__cvta_generic_to_shared(As);
    const unsigned sB = (unsigned)__cvta_generic_to_shared(Bs);

    auto issue = [&](int k0, int buf) {
        #pragma unroll
        for (int i = 0; i < 4; i++) {            // A: 1024 x 16B
            int idx = tid + i * 256;
            int r = idx >> 3, cg = (idx & 7) << 3;
            cp16(sA + (buf * 128 * SA + r * SA + cg) * 2, &Ag[r * 256 + k0 + cg]);
        }
        #pragma unroll
        for (int i = 0; i < 2; i++) {            // B: 512 x 16B
            int idx = tid + i * 256;
            int r = idx >> 3, cg = (idx & 7) << 3;
            cp16(sB + (buf * 64 * SA + r * SA + cg) * 2, &Bg[r * 256 + k0 + cg]);
        }
        CP_COMMIT();
    };

    float acc[8][4] = {};
    issue(0, 0);
    for (int c = 0; c < 4; c++) {
        if (c < 3) issue((c + 1) * 64, (c + 1) & 1);
        if (c < 3) { CP_WAIT(1); } else { CP_WAIT(0); }
        __syncthreads();
        const __nv_bfloat16* Ab = As + (c & 1) * 128 * SA;
        const __nv_bfloat16* Bb = Bs + (c & 1) * 64 * SA;
        #pragma unroll
        for (int kk = 0; kk < 4; kk++) {
            const int d = (kk << 4) + (tg << 1);
            unsigned a[4];
            a[0] = *(const unsigned*)&Ab[(qr0 + g) * SA + d];
            a[1] = *(const unsigned*)&Ab[(qr0 + g + 8) * SA + d];
            a[2] = *(const unsigned*)&Ab[(qr0 + g) * SA + d + 8];
            a[3] = *(const unsigned*)&Ab[(qr0 + g + 8) * SA + d + 8];
            #pragma unroll
            for (int t = 0; t < 8; t++) {
                int j = (t << 3) + g;
                unsigned b0 = *(const unsigned*)&Bb[j * SA + d];
                unsigned b1 = *(const unsigned*)&Bb[j * SA + d + 8];
                mma16816(acc[t], a, b0, b1);
            }
        }
        __syncthreads();
    }

    // stage C tile fp32 (smem reused)
    #pragma unroll
    for (int t = 0; t < 8; t++) {
        int col = (t << 3) + (tg << 1);
        *(float2*)&Cs[(qr0 + g) * 68 + col]     = make_float2(acc[t][0], acc[t][1]);
        *(float2*)&Cs[(qr0 + g + 8) * 68 + col] = make_float2(acc[t][2], acc[t][3]);
    }
    __syncthreads();

    const int type = (n0 >> 6) % 3;    // 0=q 1=k 2=v
    const int head = n0 / 192;
    const int bh   = (b << 2) + head;

    if (type != 2) {
        const int d2 = tid & 31;
        const float bb0 = bqkv[n0 + 2 * d2];
        const float bb1 = bqkv[n0 + 2 * d2 + 1];
        const float sc = (type == 0) ? QKSCALE : 1.0f;
        __nv_bfloat16* dst = (type == 0) ? g_Qh : g_Kh;
        #pragma unroll
        for (int i = 0; i < 16; i++) {
            int r = (tid >> 5) + i * 8;
            float f0 = (Cs[r * 68 + 2 * d2]     + bb0) * sc;
            float f1 = (Cs[r * 68 + 2 * d2 + 1] + bb1) * sc;
            *(unsigned*)&dst[((size_t)(bh << 10) + s0 + r) * 64 + 2 * d2] =
                pack_bf16(f0, f1);
        }
    } else {
        const int sp = tid & 63;               // s-pair 0..63
        #pragma unroll
        for (int i = 0; i < 16; i++) {
            int d = (tid >> 6) + i * 4;
            float bb = bqkv[n0 + d];
            float f0 = Cs[(2 * sp) * 68 + d]     + bb;
            float f1 = Cs[(2 * sp + 1) * 68 + d] + bb;
            *(unsigned*)&g_Vth[((size_t)(bh << 6) + d) * 1024 + s0 + 2 * sp] =
                pack_bf16(f0, f1);
        }
    }
}

// ---------------------------------------------------------------------------
// Kernel 2: flash attention.  CTA = 128 q-rows x bh.  8 warps, each warp owns
// 16 q-rows x ALL 64 keys -> softmax entirely in registers, P stays in
// registers (C-fragment == A-fragment layout).  K/V cp.async double-buffered.
// ---------------------------------------------------------------------------
#define SB 72

__global__ __launch_bounds__(256, 2) void flash_attn()
{
    __shared__ __align__(16) __nv_bfloat16 Ks[2][64 * SB];
    __shared__ __align__(16) __nv_bfloat16 Vt[2][64 * SB];

    const int qt  = blockIdx.x;        // 8
    const int bh  = blockIdx.y;        // 128
    const int tid = threadIdx.x;
    const int w   = tid >> 5, lane = tid & 31;
    const int g   = lane >> 2, tg = lane & 3;
    const int qr0 = w << 4;

    // Q fragments (register-resident whole kernel)
    const __nv_bfloat16* Qg = g_Qh + ((size_t)(bh << 10) + (qt << 7)) * 64;
    unsigned qa[4][4];
    #pragma unroll
    for (int kk = 0; kk < 4; kk++) {
        int c = (kk << 4) + (tg << 1);
        qa[kk][0] = *(const unsigned*)&Qg[(qr0 + g) * 64 + c];
        qa[kk][1] = *(const unsigned*)&Qg[(qr0 + g + 8) * 64 + c];
        qa[kk][2] = *(const unsigned*)&Qg[(qr0 + g) * 64 + c + 8];
        qa[kk][3] = *(const unsigned*)&Qg[(qr0 + g + 8) * 64 + c + 8];
    }

    const __nv_bfloat16* Kg0 = g_Kh  + (size_t)(bh << 10) * 64;   // [s][d]
    const __nv_bfloat16* Vg0 = g_Vth + (size_t)(bh << 6) * 1024;  // [d][s]
    const unsigned sK = (unsigned)__cvta_generic_to_shared(&Ks[0][0]);
    const unsigned sV = (unsigned)__cvta_generic_to_shared(&Vt[0][0]);

    auto issue = [&](int kt, int buf) {
        const __nv_bfloat16* Kg = Kg0 + (size_t)(kt << 6) * 64;
        const __nv_bfloat16* Vg = Vg0 + (kt << 6);
        #pragma unroll
        for (int i = 0; i < 2; i++) {
            int idx = tid + i * 256;              // 512 x 16B each
            int r = idx >> 3, cg = (idx & 7) << 3;
            cp16(sK + (buf * 64 * SB + r * SB + cg) * 2, &Kg[r * 64 + cg]);
            cp16(sV + (buf * 64 * SB + r * SB + cg) * 2, &Vg[r * 1024 + cg]);
        }
        CP_COMMIT();
    };

    float m0 = -1e30f, m1 = -1e30f, l0 = 0.0f, l1 = 0.0f;
    float o[8][4] = {};

    issue(0, 0);
    for (int kt = 0; kt < 16; kt++) {
        if (kt < 15) issue(kt + 1, (kt + 1) & 1);
        if (kt < 15) { CP_WAIT(1); } else { CP_WAIT(0); }
        __syncthreads();
        const __nv_bfloat16* Kb = &Ks[kt & 1][0];
        const __nv_bfloat16* Vb = &Vt[kt & 1][0];

        // S = Q K^T (Q pre-scaled): 16x64 per warp
        float sc[8][4];
        #pragma unroll
        for (int t = 0; t < 8; t++)
            #pragma unroll
            for (int i = 0; i < 4; i++) sc[t][i] = 0.0f;
        #pragma unroll
        for (int kk = 0; kk < 4; kk++) {
            const int d = (kk << 4) + (tg << 1);
            #pragma unroll
            for (int t = 0; t < 8; t++) {
                int j = (t << 3) + g;
                unsigned b0 = *(const unsigned*)&Kb[j * SB + d];
                unsigned b1 = *(const unsigned*)&Kb[j * SB + d + 8];
                mma16816(sc[t], qa[kk], b0, b1);
            }
        }

        // register softmax: rows g (sc[t][0..1]) and g+8 (sc[t][2..3])
        float mx0 = -1e30f, mx1 = -1e30f;
        #pragma unroll
        for (int t = 0; t < 8; t++) {
            mx0 = fmaxf(mx0, fmaxf(sc[t][0], sc[t][1]));
            mx1 = fmaxf(mx1, fmaxf(sc[t][2], sc[t][3]));
        }
        mx0 = fmaxf(mx0, __shfl_xor_sync(0xffffffffu, mx0, 1));
        mx0 = fmaxf(mx0, __shfl_xor_sync(0xffffffffu, mx0, 2));
        mx1 = fmaxf(mx1, __shfl_xor_sync(0xffffffffu, mx1, 1));
        mx1 = fmaxf(mx1, __shfl_xor_sync(0xffffffffu, mx1, 2));
        const float mn0 = fmaxf(m0, mx0);
        const float mn1 = fmaxf(m1, mx1);

        float sum0 = 0.0f, sum1 = 0.0f;
        unsigned pa[4][4];
        #pragma unroll
        for (int t = 0; t < 8; t++) {
            float p0 = __expf(sc[t][0] - mn0);
            float p1 = __expf(sc[t][1] - mn0);
            float p2 = __expf(sc[t][2] - mn1);
            float p3 = __expf(sc[t][3] - mn1);
            sum0 += p0 + p1; sum1 += p2 + p3;
            int kk = t >> 1;
            if ((t & 1) == 0) {
                pa[kk][0] = pack_bf16(p0, p1);
                pa[kk][1] = pack_bf16(p2, p3);
            } else {
                pa[kk][2] = pack_bf16(p0, p1);
                pa[kk][3] = pack_bf16(p2, p3);
            }
        }
        sum0 += __shfl_xor_sync(0xffffffffu, sum0, 1);
        sum0 += __shfl_xor_sync(0xffffffffu, sum0, 2);
        sum1 += __shfl_xor_sync(0xffffffffu, sum1, 1);
        sum1 += __shfl_xor_sync(0xffffffffu, sum1, 2);

        const float al0 = __expf(m0 - mn0);
        const float al1 = __expf(m1 - mn1);
        l0 = l0 * al0 + sum0;  l1 = l1 * al1 + sum1;
        m0 = mn0;  m1 = mn1;
        #pragma unroll
        for (int t = 0; t < 8; t++) {
            o[t][0] *= al0; o[t][1] *= al0;
            o[t][2] *= al1; o[t][3] *= al1;
        }

        // O += P V : PV with P fragments straight from registers
        #pragma unroll
        for (int kk = 0; kk < 4; kk++) {
            const int jj = (kk << 4) + (tg << 1);
            #pragma unroll
            for (int t = 0; t < 8; t++) {
                int dr = (t << 3) + g;
                unsigned b0 = *(const unsigned*)&Vb[dr * SB + jj];
                unsigned b1 = *(const unsigned*)&Vb[dr * SB + jj + 8];
                mma16816(o[t], pa[kk], b0, b1);
            }
        }
        __syncthreads();
    }

    // epilogue: normalize, write bf16 [b, s, h*64+d]
    const float inv0 = 1.0f / l0;
    const float inv1 = 1.0f / l1;
    const int b = bh >> 2, h = bh & 3;
    const int s0 = qt << 7;
    #pragma unroll
    for (int t = 0; t < 8; t++) {
        int col = (h << 6) + (t << 3) + (tg << 1);
        *(unsigned*)&g_Oh[((size_t)(b << 10) + s0 + qr0 + g) * 256 + col] =
            pack_bf16(o[t][0] * inv0, o[t][1] * inv0);
        *(unsigned*)&g_Oh[((size_t)(b << 10) + s0 + qr0 + g + 8) * 256 + col] =
            pack_bf16(o[t][2] * inv1, o[t][3] * inv1);
    }
}

// ---------------------------------------------------------------------------
// Kernel 3: out = Oh @ Wout^T + b_out + xs -> [b,c,s].  CTA 128x64, cp.async.
// ---------------------------------------------------------------------------
__global__ __launch_bounds__(256, 2) void out_mma(
    const float* __restrict__ x, const float* __restrict__ bout,
    float* __restrict__ out)
{
    extern __shared__ __align__(16) char smraw[];
    __nv_bfloat16* As = (__nv_bfloat16*)smraw;
    __nv_bfloat16* Bs = As + 2 * 128 * SA;
    float* Cs = (float*)smraw;

    const int m0 = blockIdx.x * 128;   // 256
    const int n0 = blockIdx.y * 64;    // 4
    const int b  = m0 >> 10;
    const int s0 = m0 & 1023;
    const int tid = threadIdx.x;
    const int w = tid >> 5, lane = tid & 31;
    const int g = lane >> 2, tg = lane & 3;
    const int qr0 = w << 4;

    const __nv_bfloat16* Ag = g_Oh + (size_t)m0 * 256;
    const __nv_bfloat16* Bg = g_Woh + (size_t)n0 * 256;
    const unsigned sA = (unsigned)__cvta_generic_to_shared(As);
    const unsigned sB = (unsigned)__cvta_generic_to_shared(Bs);

    auto issue = [&](int k0, int buf) {
        #pragma unroll
        for (int i = 0; i < 4; i++) {
            int idx = tid + i * 256;
            int r = idx >> 3, cg = (idx & 7) << 3;
            cp16(sA + (buf * 128 * SA + r * SA + cg) * 2, &Ag[r * 256 + k0 + cg]);
        }
        #pragma unroll
        for (int i = 0; i < 2; i++) {
            int idx = tid + i * 256;
            int r = idx >> 3, cg = (idx & 7) << 3;
            cp16(sB + (buf * 64 * SA + r * SA + cg) * 2, &Bg[r * 256 + k0 + cg]);
        }
        CP_COMMIT();
    };

    float acc[8][4] = {};
    issue(0, 0);
    for (int c = 0; c < 4; c++) {
        if (c < 3) issue((c + 1) * 64, (c + 1) & 1);
        if (c < 3) { CP_WAIT(1); } else { CP_WAIT(0); }
        __syncthreads();
        const __nv_bfloat16* Ab = As + (c & 1) * 128 * SA;
        const __nv_bfloat16* Bb = Bs + (c & 1) * 64 * SA;
        #pragma unroll
        for (int kk = 0; kk < 4; kk++) {
            const int d = (kk << 4) + (tg << 1);
            unsigned a[4];
            a[0] = *(const unsigned*)&Ab[(qr0 + g) * SA + d];
            a[1] = *(const unsigned*)&Ab[(qr0 + g + 8) * SA + d];
            a[2] = *(const unsigned*)&Ab[(qr0 + g) * SA + d + 8];
            a[3] = *(const unsigned*)&Ab[(qr0 + g + 8) * SA + d + 8];
            #pragma unroll
            for (int t = 0; t < 8; t++) {
                int j = (t << 3) + g;
                unsigned b0 = *(const unsigned*)&Bb[j * SA + d];
                unsigned b1 = *(const unsigned*)&Bb[j * SA + d + 8];
                mma16816(acc[t], a, b0, b1);
            }
        }
        __syncthreads();
    }

    #pragma unroll
    for (int t = 0; t < 8; t++) {
        int col = (t << 3) + (tg << 1);
        *(float2*)&Cs[(qr0 + g) * 68 + col]     = make_float2(acc[t][0], acc[t][1]);
        *(float2*)&Cs[(qr0 + g + 8) * 68 + col] = make_float2(acc[t][2], acc[t][3]);
    }
    __syncthreads();

    #pragma unroll
    for (int i = 0; i < 8; i++) {
        int lin = tid + i * 256;
        int n  = lin >> 5;                 // 0..63
        int s4 = (lin & 31) << 2;          // 0..124
        float bb = bout[n0 + n];
        float4 cv = make_float4(Cs[s4 * 68 + n], Cs[(s4 + 1) * 68 + n],
                                Cs[(s4 + 2) * 68 + n], Cs[(s4 + 3) * 68 + n]);
        int gidx = ((b << 8) + n0 + n) * 1024 + s0 + s4;
        float4 xv = *(const float4*)&x[gidx];
        *(float4*)&out[gidx] = make_float4(cv.x + bb + xv.x, cv.y + bb + xv.y,
                                           cv.z + bb + xv.z, cv.w + bb + xv.w);
    }
}

// ---------------------------------------------------------------------------
extern "C" void kernel_launch(void* const* d_in, const int* in_sizes, int n_in,
                              void* d_out, int out_size)
{
    const float* x    = (const float*)d_in[0];
    const float* Wqkv = (const float*)d_in[1];
    const float* bqkv = (const float*)d_in[2];
    const float* Wout = (const float*)d_in[3];
    const float* bout = (const float*)d_in[4];
    float* out = (float*)d_out;

    __nv_bfloat16 *pXh, *pWqh, *pWoh;
    cudaGetSymbolAddress((void**)&pXh,  g_Xh);
    cudaGetSymbolAddress((void**)&pWqh, g_Wqh);
    cudaGetSymbolAddress((void**)&pWoh, g_Woh);

    transpose_bf16<<<dim3(32, 8, 32), 256>>>(x,    pXh,  256, 1024);
    transpose_bf16<<<dim3(24, 8, 1),  256>>>(Wqkv, pWqh, 256, 768);
    transpose_bf16<<<dim3(8, 8, 1),   256>>>(Wout, pWoh, 256, 256);

    const int gsm = (2 * 128 * SA + 2 * 64 * SA) * (int)sizeof(__nv_bfloat16);
    cudaFuncSetAttribute(qkv_mma, cudaFuncAttributeMaxDynamicSharedMemorySize, gsm);
    cudaFuncSetAttribute(out_mma, cudaFuncAttributeMaxDynamicSharedMemorySize, gsm);

    qkv_mma<<<dim3(256, 12), 256, gsm>>>(bqkv);
    flash_attn<<<dim3(8, 128), 256>>>();
    out_mma<<<dim3(256, 4), 256, gsm>>>(x, bout, out);
}